// round 17
// baseline (speedup 1.0000x reference)
#include <cuda_runtime.h>
#include <cfloat>

// Problem constants (fixed shapes per reference):
// B=16, C=3, H=W=256 (HW=65536), NC=35, disc_w has C+NC=38 weights.
#define B_   16
#define C_   3
#define HW_  65536
#define NC_  35
#define NW_  38
#define NPIX (B_ * HW_)          // 1,048,576 pixels
#define PIX_PER_THREAD 8         // 8 ADJACENT pixels = 2 consecutive float4/channel
#define THREADS 256
#define NBLOCKS (NPIX / PIX_PER_THREAD / THREADS)   // 512
#define K_PERSIST 16             // seg channels [0,16) default policy (L2-resident)

__device__ double   g_acc   = 0.0;
__device__ unsigned g_count = 0;

__device__ __forceinline__ float4 seg_load(const float4* p, int k) {
    return (k < K_PERSIST) ? __ldg(p) : __ldcs(p);
}

__global__ __launch_bounds__(THREADS, 3) void labelmix_kernel(
    const float* __restrict__ real_img,
    const float* __restrict__ gen_img,
    const float* __restrict__ seg,
    const float* __restrict__ rdisc,
    const float* __restrict__ gdisc,
    const float* __restrict__ disc_w,
    const int*   __restrict__ class_lut,
    float*       __restrict__ out)
{
    __shared__ float sw[NW_];
    __shared__ float slut[NC_];
    __shared__ double warp_part[THREADS / 32];

    int t = threadIdx.x;
    if (t < NW_) sw[t] = disc_w[t];
    if (t < NC_) slut[t] = (float)class_lut[t];
    __syncthreads();

    int tid = blockIdx.x * blockDim.x + t;
    int p8  = tid * PIX_PER_THREAD;            // global pixel index (multiple of 8)
    int b   = p8 >> 16;                        // p8 / HW_
    int hw  = p8 & (HW_ - 1);

    const float* segp = seg      + ((size_t)b * NC_) * HW_ + hw;
    const float* rip  = real_img + ((size_t)b * C_ ) * HW_ + hw;
    const float* gip  = gen_img  + ((size_t)b * C_ ) * HW_ + hw;
    const float* rdp  = rdisc    + (size_t)b * HW_ + hw;
    const float* gdp  = gdisc    + (size_t)b * HW_ + hw;

    // ---- seg channels: serial walk with 1-channel software prefetch ----
    // Steady state: 4 LDG.128 in flight per thread (k+1 issued before k consumed).
    // Policy: [0,K_PERSIST) default (L2-resident across replays), rest evict-first.
    float mx[PIX_PER_THREAD];
    float acc[PIX_PER_THREAD];
    int   ix[PIX_PER_THREAD];
    #pragma unroll
    for (int j = 0; j < PIX_PER_THREAD; j++) {
        mx[j] = -FLT_MAX; acc[j] = 0.f; ix[j] = 0;
    }

    const float4* cp0 = (const float4*)segp;   // channel stride = HW_/4 float4
    const int CH4 = HW_ / 4;

    float4 sa = seg_load(cp0, 0);
    float4 sb = seg_load(cp0 + 1, 0);

    #pragma unroll
    for (int k = 0; k < NC_; k++) {
        float4 na, nb;
        if (k + 1 < NC_) {
            const float4* np = cp0 + (size_t)(k + 1) * CH4;
            na = seg_load(np, k + 1);
            nb = seg_load(np + 1, k + 1);
        }
        float s[PIX_PER_THREAD] = {sa.x, sa.y, sa.z, sa.w, sb.x, sb.y, sb.z, sb.w};
        float wk = sw[C_ + k];
        #pragma unroll
        for (int j = 0; j < PIX_PER_THREAD; j++) {
            if (s[j] > mx[j]) { mx[j] = s[j]; ix[j] = k; }   // strict > = first-max
            acc[j] = fmaf(wk, s[j], acc[j]);
        }
        if (k + 1 < NC_) { sa = na; sb = nb; }
    }

    float tm[PIX_PER_THREAD];
    #pragma unroll
    for (int j = 0; j < PIX_PER_THREAD; j++) tm[j] = slut[ix[j]];

    // ---- image channels: mixed = tm*real + (1-tm)*gen, dot with disc_w[0:3] ----
    #pragma unroll
    for (int c = 0; c < C_; c++) {
        const float4* rp = (const float4*)(rip + (size_t)c * HW_);
        const float4* gp = (const float4*)(gip + (size_t)c * HW_);
        float4 ra = __ldg(rp), rb = __ldg(rp + 1);
        float4 ga = __ldg(gp), gb = __ldg(gp + 1);
        float r[PIX_PER_THREAD] = {ra.x, ra.y, ra.z, ra.w, rb.x, rb.y, rb.z, rb.w};
        float g[PIX_PER_THREAD] = {ga.x, ga.y, ga.z, ga.w, gb.x, gb.y, gb.z, gb.w};
        float wc = sw[c];
        #pragma unroll
        for (int j = 0; j < PIX_PER_THREAD; j++)
            acc[j] = fmaf(wc, fmaf(tm[j], r[j] - g[j], g[j]), acc[j]);
    }

    // ---- mixed D output + squared error ----
    float part = 0.f;
    {
        const float4* rp = (const float4*)rdp;
        const float4* gp = (const float4*)gdp;
        float4 ra = __ldg(rp), rb = __ldg(rp + 1);
        float4 ga = __ldg(gp), gb = __ldg(gp + 1);
        float r[PIX_PER_THREAD] = {ra.x, ra.y, ra.z, ra.w, rb.x, rb.y, rb.z, rb.w};
        float g[PIX_PER_THREAD] = {ga.x, ga.y, ga.z, ga.w, gb.x, gb.y, gb.z, gb.w};
        #pragma unroll
        for (int j = 0; j < PIX_PER_THREAD; j++) {
            float d = acc[j] - fmaf(tm[j], r[j] - g[j], g[j]);
            part = fmaf(d, d, part);
        }
    }

    // ---- reduction: warp shuffle (f32) -> block (f64) -> global atomic (f64) ----
    #pragma unroll
    for (int off = 16; off > 0; off >>= 1)
        part += __shfl_down_sync(0xFFFFFFFFu, part, off);

    int warp = t >> 5;
    if ((t & 31) == 0) warp_part[warp] = (double)part;
    __syncthreads();

    if (t == 0) {
        double s = 0.0;
        #pragma unroll
        for (int wI = 0; wI < THREADS / 32; wI++) s += warp_part[wI];
        atomicAdd(&g_acc, s);
        __threadfence();
        unsigned prev = atomicAdd(&g_count, 1);
        if (prev == NBLOCKS - 1) {
            out[0] = (float)(g_acc / (double)NPIX);
            // reset for next graph replay (deterministic: exactly once per launch)
            g_acc   = 0.0;
            g_count = 0;
        }
    }
}

extern "C" void kernel_launch(void* const* d_in, const int* in_sizes, int n_in,
                              void* d_out, int out_size)
{
    const float* real_img = (const float*)d_in[0];
    const float* gen_img  = (const float*)d_in[1];
    const float* seg      = (const float*)d_in[2];
    const float* rdisc    = (const float*)d_in[3];
    const float* gdisc    = (const float*)d_in[4];
    const float* disc_w   = (const float*)d_in[5];
    const int*   class_lut= (const int*)  d_in[6];

    labelmix_kernel<<<NBLOCKS, THREADS>>>(real_img, gen_img, seg,
                                          rdisc, gdisc, disc_w, class_lut,
                                          (float*)d_out);
}